// round 15
// baseline (speedup 1.0000x reference)
#include <cuda_runtime.h>
#include <cuda_bf16.h>
#include <math.h>
#include <stdint.h>

// Problem constants (fixed by the reference: B=1, S=4096, D=2048, H=16)
#define S_LEN    4096
#define D_MODEL  2048
#define KDIM     2048
#define N_HEADS  16
#define HEAD_DIM 128

// ---------------------------------------------------------------------------
// Scratch (__device__ globals; allocation-free rule)
// ---------------------------------------------------------------------------
__device__ float g_V[(size_t)S_LEN * D_MODEL];

__device__ __nv_bfloat16 g_Xhi[(size_t)S_LEN * D_MODEL];
__device__ __nv_bfloat16 g_Xlo[(size_t)S_LEN * D_MODEL];
__device__ __nv_bfloat16 g_Ohi[(size_t)S_LEN * D_MODEL];
__device__ __nv_bfloat16 g_Olo[(size_t)S_LEN * D_MODEL];
__device__ __nv_bfloat16 g_Wthi[(size_t)4 * D_MODEL * D_MODEL];
__device__ __nv_bfloat16 g_Wtlo[(size_t)4 * D_MODEL * D_MODEL];

// attention operands (bf16 hi/lo). Q pre-scaled by 1/sqrt(hd).
__device__ __nv_bfloat16 g_Qhi[(size_t)S_LEN * D_MODEL];
__device__ __nv_bfloat16 g_Qlo[(size_t)S_LEN * D_MODEL];
__device__ __nv_bfloat16 g_Khi[(size_t)S_LEN * D_MODEL];
__device__ __nv_bfloat16 g_Klo[(size_t)S_LEN * D_MODEL];
// V transposed per head: Vt[c][s] where c = h*128 + d  -> [D_MODEL][S_LEN]
__device__ __nv_bfloat16 g_Vthi[(size_t)D_MODEL * S_LEN];
__device__ __nv_bfloat16 g_Vtlo[(size_t)D_MODEL * S_LEN];

// ---------------------------------------------------------------------------
// Portable helpers (sm_80+): cp.async + mma.sync bf16 + ldmatrix
// ---------------------------------------------------------------------------
__device__ __forceinline__ uint32_t smem_to_u32(const void* p) {
    uint32_t a;
    asm("{ .reg .u64 t; cvta.to.shared.u64 t, %1; cvt.u32.u64 %0, t; }" : "=r"(a) : "l"(p));
    return a;
}
__device__ __forceinline__ void cp_async16(uint32_t dst, const void* src) {
    asm volatile("cp.async.cg.shared.global [%0], [%1], 16;" :: "r"(dst), "l"(src));
}
#define CP_COMMIT() asm volatile("cp.async.commit_group;" ::: "memory")
#define CP_WAIT1()  asm volatile("cp.async.wait_group 1;" ::: "memory")
#define CP_WAIT0()  asm volatile("cp.async.wait_group 0;" ::: "memory")

__device__ __forceinline__ void mma_bf16(float* c, const uint32_t* a, const uint32_t* b) {
    asm volatile(
        "mma.sync.aligned.m16n8k16.row.col.f32.bf16.bf16.f32 "
        "{%0,%1,%2,%3}, {%4,%5,%6,%7}, {%8,%9}, {%0,%1,%2,%3};"
        : "+f"(c[0]), "+f"(c[1]), "+f"(c[2]), "+f"(c[3])
        : "r"(a[0]), "r"(a[1]), "r"(a[2]), "r"(a[3]), "r"(b[0]), "r"(b[1]));
}
__device__ __forceinline__ void ldsm_x4(uint32_t& r0, uint32_t& r1, uint32_t& r2, uint32_t& r3,
                                        uint32_t addr) {
    asm volatile("ldmatrix.sync.aligned.m8n8.x4.shared.b16 {%0,%1,%2,%3}, [%4];"
                 : "=r"(r0), "=r"(r1), "=r"(r2), "=r"(r3) : "r"(addr));
}
__device__ __forceinline__ uint32_t pack_bf16x2(float lo, float hi) {
    __nv_bfloat162 v = __float22bfloat162_rn(make_float2(lo, hi));
    return *reinterpret_cast<uint32_t*>(&v);
}

// ---------------------------------------------------------------------------
// Prep kernels
// ---------------------------------------------------------------------------
__global__ void split_x_kernel(const float* __restrict__ X) {
    size_t i = (size_t)blockIdx.x * blockDim.x + threadIdx.x;
    float v = X[i];
    __nv_bfloat16 h = __float2bfloat16(v);
    g_Xhi[i] = h;
    g_Xlo[i] = __float2bfloat16(v - __bfloat162float(h));
}
__global__ void wsplit_t_kernel(const float* __restrict__ Wq, const float* __restrict__ Wk,
                                const float* __restrict__ Wv, const float* __restrict__ Wo) {
    __shared__ float tile[32][33];
    const int w = blockIdx.z;
    const float* W = (w == 0) ? Wq : (w == 1) ? Wk : (w == 2) ? Wv : Wo;
    const size_t off = (size_t)w * D_MODEL * D_MODEL;
    const int n0 = blockIdx.x * 32, k0 = blockIdx.y * 32;
    const int tx = threadIdx.x, ty = threadIdx.y;  // (32, 8)
#pragma unroll
    for (int i = 0; i < 32; i += 8)
        tile[ty + i][tx] = W[(size_t)(k0 + ty + i) * D_MODEL + n0 + tx];
    __syncthreads();
#pragma unroll
    for (int i = 0; i < 32; i += 8) {
        int n = n0 + ty + i, k = k0 + tx;
        float v = tile[tx][ty + i];
        __nv_bfloat16 h = __float2bfloat16(v);
        g_Wthi[off + (size_t)n * KDIM + k] = h;
        g_Wtlo[off + (size_t)n * KDIM + k] = __float2bfloat16(v - __bfloat162float(h));
    }
}
// V [S][D] fp32 -> Vt hi/lo [D][S] bf16 (coalesced 32x32 transpose)
__global__ void vt_split_kernel() {
    __shared__ float tile[32][33];
    const int s0 = blockIdx.y * 32, c0 = blockIdx.x * 32;
    const int tx = threadIdx.x, ty = threadIdx.y;  // (32, 8)
#pragma unroll
    for (int i = 0; i < 32; i += 8)
        tile[ty + i][tx] = g_V[(size_t)(s0 + ty + i) * D_MODEL + c0 + tx];
    __syncthreads();
#pragma unroll
    for (int i = 0; i < 32; i += 8) {
        int c = c0 + ty + i, s = s0 + tx;
        float v = tile[tx][ty + i];
        __nv_bfloat16 h = __float2bfloat16(v);
        g_Vthi[(size_t)c * S_LEN + s] = h;
        g_Vtlo[(size_t)c * S_LEN + s] = __float2bfloat16(v - __bfloat162float(h));
    }
}

// ---------------------------------------------------------------------------
// bf16x3 tensor-core GEMM core (compute accumulators for one 128x128 tile).
// Block 128x128xK64, 256 threads (8 warps 2x4), warp tile 64x32.
// K-step 64 per stage (2 stages, 144KB smem, 1 CTA/SM), ldmatrix fragment
// loads double-buffered across the 4 inner k16 steps.
// ---------------------------------------------------------------------------
#define LDSW 72                       // bf16 elems per smem row (144 B)
#define TILE_B (128 * LDSW * 2)       // 18432 B per operand tile
#define STAGE_B (4 * TILE_B)          // 73728 B
#define GEMM_SMEM (2 * STAGE_B)       // 147456 B
#define NSTAGE (KDIM / 64)            // 32

__device__ __forceinline__ void gemm_core(const __nv_bfloat16* __restrict__ Ah,
                                          const __nv_bfloat16* __restrict__ Al,
                                          const __nv_bfloat16* __restrict__ Bh,
                                          const __nv_bfloat16* __restrict__ Bl,
                                          char* sm_, float acc[4][4][4])
{
    const int t = threadIdx.x;
    const int lane = t & 31, wid = t >> 5;
    const int wm = wid >> 2, wn = wid & 3;
    const uint32_t sbase = smem_to_u32(sm_);

#pragma unroll
    for (int mi = 0; mi < 4; mi++)
#pragma unroll
        for (int ni = 0; ni < 4; ni++)
#pragma unroll
            for (int e = 0; e < 4; e++) acc[mi][ni][e] = 0.0f;

    const __nv_bfloat16* srcs[4] = { Ah, Al, Bh, Bl };

    // ldmatrix lane-address components (per warp):
    const int lr = lane & 7;
    const int lg = lane >> 3;
    const int a_row_off = (lg & 1) * 8 + lr;
    const int a_col_off = (lg >> 1) * 8;
    const int b_row_off = ((lg >> 1) & 1) * 8 + lr;
    const int b_col_off = (lg & 1) * 8;

    // stage loader: 64 k-cols = 8 x 16B chunks per row; 4 chunks per thread/op
    auto load_stage = [&](int s) {
        const int k0 = s * 64;
        const uint32_t dbase = sbase + (s & 1) * STAGE_B;
#pragma unroll
        for (int op = 0; op < 4; op++) {
#pragma unroll
            for (int i = 0; i < 4; i++) {
                const int idx = t + i * 256;
                const int row = idx >> 3, c = idx & 7;
                cp_async16(dbase + op * TILE_B + row * 144 + c * 16,
                           srcs[op] + (size_t)row * KDIM + k0 + c * 8);
            }
        }
        CP_COMMIT();
    };

    load_stage(0);

    uint32_t ah[2][4][4], al[2][4][4], bh[2][4][2], bl[2][4][2];

    for (int kt = 0; kt < NSTAGE; kt++) {
        if (kt + 1 < NSTAGE) {
            load_stage(kt + 1);
            CP_WAIT1();
        } else {
            CP_WAIT0();
        }
        __syncthreads();

        const uint32_t stb = sbase + (kt & 1) * STAGE_B;
        const uint32_t sAh = stb;
        const uint32_t sAl = stb + TILE_B;
        const uint32_t sBh = stb + 2 * TILE_B;
        const uint32_t sBl = stb + 3 * TILE_B;

        // fragment loader for inner k16 step `ks` into buffer `fb`
        auto load_frags = [&](int ks, int fb) {
            const int kbase = ks * 16;
#pragma unroll
            for (int mi = 0; mi < 4; mi++) {
                const int r = wm * 64 + mi * 16 + a_row_off;
                const uint32_t off = (uint32_t)(r * LDSW + kbase + a_col_off) * 2;
                ldsm_x4(ah[fb][mi][0], ah[fb][mi][1], ah[fb][mi][2], ah[fb][mi][3], sAh + off);
                ldsm_x4(al[fb][mi][0], al[fb][mi][1], al[fb][mi][2], al[fb][mi][3], sAl + off);
            }
#pragma unroll
            for (int pair = 0; pair < 2; pair++) {
                const int n = wn * 32 + pair * 16 + b_row_off;
                const uint32_t off = (uint32_t)(n * LDSW + kbase + b_col_off) * 2;
                ldsm_x4(bh[fb][2 * pair][0], bh[fb][2 * pair][1],
                        bh[fb][2 * pair + 1][0], bh[fb][2 * pair + 1][1], sBh + off);
                ldsm_x4(bl[fb][2 * pair][0], bl[fb][2 * pair][1],
                        bl[fb][2 * pair + 1][0], bl[fb][2 * pair + 1][1], sBl + off);
            }
        };

        load_frags(0, 0);
#pragma unroll
        for (int ks = 0; ks < 4; ks++) {
            const int fb = ks & 1;
            if (ks < 3) load_frags(ks + 1, fb ^ 1);
#pragma unroll
            for (int mi = 0; mi < 4; mi++)
#pragma unroll
                for (int ni = 0; ni < 4; ni++) {
                    mma_bf16(acc[mi][ni], ah[fb][mi], bh[fb][ni]);
                    mma_bf16(acc[mi][ni], ah[fb][mi], bl[fb][ni]);
                    mma_bf16(acc[mi][ni], al[fb][mi], bh[fb][ni]);
                }
        }
        __syncthreads();
    }
}

// Fused QKV: z=0 -> Q (scaled, bf16 split out), z=1 -> K (split out), z=2 -> V (fp32)
__global__ __launch_bounds__(256, 1)
void qkv_gemm_fused()
{
    extern __shared__ char sm_[];
    const int z = blockIdx.z;
    const int bm = blockIdx.y, bn = blockIdx.x;
    const size_t woff = (size_t)z * D_MODEL * D_MODEL;

    float acc[4][4][4];
    gemm_core(g_Xhi + (size_t)(bm * 128) * KDIM,
              g_Xlo + (size_t)(bm * 128) * KDIM,
              g_Wthi + woff + (size_t)(bn * 128) * KDIM,
              g_Wtlo + woff + (size_t)(bn * 128) * KDIM,
              sm_, acc);

    const int t = threadIdx.x;
    const int lane = t & 31, wid = t >> 5;
    const int wm = wid >> 2, wn = wid & 3;
    const int rsub = lane >> 2, csub = (lane & 3) * 2;
    const int rowB = bm * 128 + wm * 64;
    const int colB = bn * 128 + wn * 32;

    if (z == 2) {
        float* Cb = g_V + (size_t)rowB * D_MODEL + colB;
#pragma unroll
        for (int mi = 0; mi < 4; mi++)
#pragma unroll
            for (int ni = 0; ni < 4; ni++) {
                const int row = mi * 16 + rsub;
                const int col = ni * 8 + csub;
                *reinterpret_cast<float2*>(Cb + (size_t)row * D_MODEL + col) =
                    make_float2(acc[mi][ni][0], acc[mi][ni][1]);
                *reinterpret_cast<float2*>(Cb + (size_t)(row + 8) * D_MODEL + col) =
                    make_float2(acc[mi][ni][2], acc[mi][ni][3]);
            }
    } else {
        const float scale = (z == 0) ? 0.08838834764831845f : 1.0f;
        __nv_bfloat16* Hi = (z == 0) ? g_Qhi : g_Khi;
        __nv_bfloat16* Lo = (z == 0) ? g_Qlo : g_Klo;
#pragma unroll
        for (int mi = 0; mi < 4; mi++)
#pragma unroll
            for (int ni = 0; ni < 4; ni++) {
                const int row = rowB + mi * 16 + rsub;
                const int col = colB + ni * 8 + csub;
#pragma unroll
                for (int half = 0; half < 2; half++) {
                    const int r = row + half * 8;
                    float v0 = acc[mi][ni][2 * half + 0] * scale;
                    float v1 = acc[mi][ni][2 * half + 1] * scale;
                    float h0 = __bfloat162float(__float2bfloat16(v0));
                    float h1 = __bfloat162float(__float2bfloat16(v1));
                    *reinterpret_cast<uint32_t*>(Hi + (size_t)r * D_MODEL + col) =
                        pack_bf16x2(h0, h1);
                    *reinterpret_cast<uint32_t*>(Lo + (size_t)r * D_MODEL + col) =
                        pack_bf16x2(v0 - h0, v1 - h1);
                }
            }
    }
}

// Output projection: fp32 epilogue straight to harness output
__global__ __launch_bounds__(256, 1)
void out_gemm(float* __restrict__ out)
{
    extern __shared__ char sm_[];
    const int bm = blockIdx.y, bn = blockIdx.x;
    const size_t woff = (size_t)3 * D_MODEL * D_MODEL;

    float acc[4][4][4];
    gemm_core(g_Ohi + (size_t)(bm * 128) * KDIM,
              g_Olo + (size_t)(bm * 128) * KDIM,
              g_Wthi + woff + (size_t)(bn * 128) * KDIM,
              g_Wtlo + woff + (size_t)(bn * 128) * KDIM,
              sm_, acc);

    const int t = threadIdx.x;
    const int lane = t & 31, wid = t >> 5;
    const int wm = wid >> 2, wn = wid & 3;
    const int rsub = lane >> 2, csub = (lane & 3) * 2;

    float* Cb = out + (size_t)(bm * 128 + wm * 64) * D_MODEL + bn * 128 + wn * 32;
#pragma unroll
    for (int mi = 0; mi < 4; mi++)
#pragma unroll
        for (int ni = 0; ni < 4; ni++) {
            const int row = mi * 16 + rsub;
            const int col = ni * 8 + csub;
            *reinterpret_cast<float2*>(Cb + (size_t)row * D_MODEL + col) =
                make_float2(acc[mi][ni][0], acc[mi][ni][1]);
            *reinterpret_cast<float2*>(Cb + (size_t)(row + 8) * D_MODEL + col) =
                make_float2(acc[mi][ni][2], acc[mi][ni][3]);
        }
}

// ---------------------------------------------------------------------------
// FA2-style attention on mma.sync (bf16 split precision).
// CTA = 128 queries x 1 head, 256 threads, 8 warps x 16 query rows.
// KV tiles of 64 keys, DOUBLE-BUFFERED via cp.async. Fragment loads via
// ldmatrix.x4. Online softmax in fp32; P kept in registers.
// Epilogue writes O directly as bf16 hi/lo splits.
// ---------------------------------------------------------------------------
#define AQ 128
#define AK 64
#define QSTR 136   // bf16 elems per Q/K smem row (272 B) -> conflict-free
#define VSTR 72    // bf16 elems per Vt smem row (144 B) -> conflict-free

#define SM_QHI 0
#define SM_QLO (SM_QHI + AQ * QSTR * 2)          // 34816
#define SM_KV  (SM_QLO + AQ * QSTR * 2)          // 69632: start of KV stages
#define KV_KHI 0
#define KV_KLO (KV_KHI + AK * QSTR * 2)          // 17408
#define KV_VHI (KV_KLO + AK * QSTR * 2)          // 34816
#define KV_VLO (KV_VHI + HEAD_DIM * VSTR * 2)    // 53248
#define KV_STAGE (KV_VLO + HEAD_DIM * VSTR * 2)  // 71680
#define ATT_SMEM (SM_KV + 2 * KV_STAGE)          // 212992

__global__ __launch_bounds__(256, 1)
void mha_fa_mma()
{
    extern __shared__ char sm_[];
    const uint32_t sbase = smem_to_u32(sm_);
    const int t = threadIdx.x;
    const int lane = t & 31, wid = t >> 5;
    const int ib = gridDim.x - 1 - blockIdx.x;   // reversed: long CTAs first
    const int h = blockIdx.y;
    const int q0 = ib * AQ;
    const int rsub = lane >> 2, csub = (lane & 3) * 2;

    // ldmatrix lane-address components
    const int lr = lane & 7;
    const int lg = lane >> 3;
    const int a_row_off = (lg & 1) * 8 + lr;     // A operand (Q)
    const int a_col_off = (lg >> 1) * 8;
    const int b_row_off = ((lg >> 1) & 1) * 8 + lr;  // B operand (K / Vt)
    const int b_col_off = (lg & 1) * 8;

    const uint32_t sQh = sbase + SM_QHI;
    const uint32_t sQl = sbase + SM_QLO;

    // ---- load Q tile (once), group 0 ----
    {
        const size_t gq = (size_t)q0 * D_MODEL + (size_t)h * HEAD_DIM;
#pragma unroll
        for (int i = 0; i < 8; i++) {
            const int idx = t + i * 256;
            const int row = idx >> 4, c = idx & 15;
            cp_async16(sQh + row * (QSTR * 2) + c * 16,
                       g_Qhi + gq + (size_t)row * D_MODEL + c * 8);
            cp_async16(sQl + row * (QSTR * 2) + c * 16,
                       g_Qlo + gq + (size_t)row * D_MODEL + c * 8);
        }
        CP_COMMIT();
    }

    const int nTiles = 2 * ib + 2;

    // ---- helper lambda: issue K/V loads for tile jb into given stage ----
    auto load_kv = [&](int jb, int stage) {
        const uint32_t kvb = sbase + SM_KV + stage * KV_STAGE;
        const int k0 = jb * AK;
        const size_t gk = (size_t)k0 * D_MODEL + (size_t)h * HEAD_DIM;
#pragma unroll
        for (int i = 0; i < 4; i++) {
            const int idx = t + i * 256;
            const int row = idx >> 4, c = idx & 15;
            cp_async16(kvb + KV_KHI + row * (QSTR * 2) + c * 16,
                       g_Khi + gk + (size_t)row * D_MODEL + c * 8);
            cp_async16(kvb + KV_KLO + row * (QSTR * 2) + c * 16,
                       g_Klo + gk + (size_t)row * D_MODEL + c * 8);
        }
        const size_t gv = (size_t)h * HEAD_DIM * S_LEN + k0;
#pragma unroll
        for (int i = 0; i < 4; i++) {
            const int idx = t + i * 256;
            const int row = idx >> 3, c = idx & 7;
            cp_async16(kvb + KV_VHI + row * (VSTR * 2) + c * 16,
                       g_Vthi + gv + (size_t)row * S_LEN + c * 8);
            cp_async16(kvb + KV_VLO + row * (VSTR * 2) + c * 16,
                       g_Vtlo + gv + (size_t)row * S_LEN + c * 8);
        }
        CP_COMMIT();
    };

    // preload tile 0 into stage 0 (group 1)
    load_kv(0, 0);

    float accO[16][4];
#pragma unroll
    for (int j = 0; j < 16; j++)
#pragma unroll
        for (int e = 0; e < 4; e++) accO[j][e] = 0.0f;
    float m0 = -1e30f, m1 = -1e30f, l0 = 0.0f, l1 = 0.0f;

    for (int jb = 0; jb < nTiles; jb++) {
        const int buf = jb & 1;
        if (jb + 1 < nTiles) {
            load_kv(jb + 1, buf ^ 1);
            CP_WAIT1();
        } else {
            CP_WAIT0();
        }
        __syncthreads();

        const uint32_t kvb = sbase + SM_KV + buf * KV_STAGE;
        const uint32_t sKh = kvb + KV_KHI;
        const uint32_t sKl = kvb + KV_KLO;
        const uint32_t sVh = kvb + KV_VHI;
        const uint32_t sVl = kvb + KV_VLO;
        const int k0 = jb * AK;

        // ---- S = Q K^T (bf16x3, ldmatrix fragments) ----
        float accS[8][4];
#pragma unroll
        for (int j = 0; j < 8; j++)
#pragma unroll
            for (int e = 0; e < 4; e++) accS[j][e] = 0.0f;

#pragma unroll
        for (int ks = 0; ks < 8; ks++) {
            const int kbase = ks * 16;
            uint32_t ah[4], al[4];
            {
                const int r = wid * 16 + a_row_off;
                const uint32_t off = (uint32_t)(r * QSTR + kbase + a_col_off) * 2;
                ldsm_x4(ah[0], ah[1], ah[2], ah[3], sQh + off);
                ldsm_x4(al[0], al[1], al[2], al[3], sQl + off);
            }
#pragma unroll
            for (int pair = 0; pair < 4; pair++) {
                const int n = pair * 16 + b_row_off;
                const uint32_t off = (uint32_t)(n * QSTR + kbase + b_col_off) * 2;
                uint32_t bh0[2], bh1[2], bl0[2], bl1[2];
                ldsm_x4(bh0[0], bh0[1], bh1[0], bh1[1], sKh + off);
                ldsm_x4(bl0[0], bl0[1], bl1[0], bl1[1], sKl + off);
                mma_bf16(accS[2 * pair], ah, bh0);
                mma_bf16(accS[2 * pair], ah, bl0);
                mma_bf16(accS[2 * pair], al, bh0);
                mma_bf16(accS[2 * pair + 1], ah, bh1);
                mma_bf16(accS[2 * pair + 1], ah, bl1);
                mma_bf16(accS[2 * pair + 1], al, bh1);
            }
        }

        // ---- causal mask (only the two diagonal tiles) ----
        if (jb >= 2 * ib) {
            const int row0 = q0 + wid * 16 + rsub;
            const int row1 = row0 + 8;
#pragma unroll
            for (int j = 0; j < 8; j++) {
                const int c0 = k0 + j * 8 + csub;
                if (c0 > row0)     accS[j][0] = -1e30f;
                if (c0 + 1 > row0) accS[j][1] = -1e30f;
                if (c0 > row1)     accS[j][2] = -1e30f;
                if (c0 + 1 > row1) accS[j][3] = -1e30f;
            }
        }

        // ---- online softmax ----
        float mx0 = -1e30f, mx1 = -1e30f;
#pragma unroll
        for (int j = 0; j < 8; j++) {
            mx0 = fmaxf(mx0, fmaxf(accS[j][0], accS[j][1]));
            mx1 = fmaxf(mx1, fmaxf(accS[j][2], accS[j][3]));
        }
        mx0 = fmaxf(mx0, __shfl_xor_sync(0xffffffffu, mx0, 1));
        mx0 = fmaxf(mx0, __shfl_xor_sync(0xffffffffu, mx0, 2));
        mx1 = fmaxf(mx1, __shfl_xor_sync(0xffffffffu, mx1, 1));
        mx1 = fmaxf(mx1, __shfl_xor_sync(0xffffffffu, mx1, 2));

        const float mn0 = fmaxf(m0, mx0);
        const float mn1 = fmaxf(m1, mx1);
        const float al0 = __expf(m0 - mn0);
        const float al1 = __expf(m1 - mn1);
        m0 = mn0; m1 = mn1;

        float s0 = 0.0f, s1 = 0.0f;
#pragma unroll
        for (int j = 0; j < 8; j++) {
            accS[j][0] = __expf(accS[j][0] - m0);
            accS[j][1] = __expf(accS[j][1] - m0);
            accS[j][2] = __expf(accS[j][2] - m1);
            accS[j][3] = __expf(accS[j][3] - m1);
            s0 += accS[j][0] + accS[j][1];
            s1 += accS[j][2] + accS[j][3];
        }
        s0 += __shfl_xor_sync(0xffffffffu, s0, 1);
        s0 += __shfl_xor_sync(0xffffffffu, s0, 2);
        s1 += __shfl_xor_sync(0xffffffffu, s1, 1);
        s1 += __shfl_xor_sync(0xffffffffu, s1, 2);
        l0 = l0 * al0 + s0;
        l1 = l1 * al1 + s1;

#pragma unroll
        for (int j = 0; j < 16; j++) {
            accO[j][0] *= al0; accO[j][1] *= al0;
            accO[j][2] *= al1; accO[j][3] *= al1;
        }

        // ---- O += P V (bf16x3; P fragments straight from accS) ----
#pragma unroll
        for (int ks = 0; ks < 4; ks++) {
            uint32_t ph[4], pl[4];
            {
                const float* f0 = accS[2 * ks];
                const float* f1 = accS[2 * ks + 1];
                float h00 = __bfloat162float(__float2bfloat16(f0[0]));
                float h01 = __bfloat162float(__float2bfloat16(f0[1]));
                float h02 = __bfloat162float(__float2bfloat16(f0[2]));
                float h03 = __bfloat162float(__float2bfloat16(f0[3]));
                float h10 = __bfloat162float(__float2bfloat16(f1[0]));
                float h11 = __bfloat162float(__float2bfloat16(f1[1]));
                float h12 = __bfloat162float(__float2bfloat16(f1[2]));
                float h13 = __bfloat162float(__float2bfloat16(f1[3]));
                ph[0] = pack_bf16x2(h00, h01);
                ph[1] = pack_bf16x2(h02, h03);
                ph[2] = pack_bf16x2(h10, h11);
                ph[3] = pack_bf16x2(h12, h13);
                pl[0] = pack_bf16x2(f0[0] - h00, f0[1] - h01);
                pl[1] = pack_bf16x2(f0[2] - h02, f0[3] - h03);
                pl[2] = pack_bf16x2(f1[0] - h10, f1[1] - h11);
                pl[3] = pack_bf16x2(f1[2] - h12, f1[3] - h13);
            }
            const int kbase = ks * 16;
#pragma unroll
            for (int pair = 0; pair < 8; pair++) {
                const int n = pair * 16 + b_row_off;
                const uint32_t off = (uint32_t)(n * VSTR + kbase + b_col_off) * 2;
                uint32_t vh0[2], vh1[2], vl0[2], vl1[2];
                ldsm_x4(vh0[0], vh0[1], vh1[0], vh1[1], sVh + off);
                ldsm_x4(vl0[0], vl0[1], vl1[0], vl1[1], sVl + off);
                mma_bf16(accO[2 * pair], ph, vh0);
                mma_bf16(accO[2 * pair], ph, vl0);
                mma_bf16(accO[2 * pair], pl, vh0);
                mma_bf16(accO[2 * pair + 1], ph, vh1);
                mma_bf16(accO[2 * pair + 1], ph, vl1);
                mma_bf16(accO[2 * pair + 1], pl, vh1);
            }
        }
        __syncthreads();   // all warps done reading this stage before it is re-filled
    }

    // ---- normalize + write O directly as bf16 hi/lo splits ----
    const float inv0 = 1.0f / l0;
    const float inv1 = 1.0f / l1;
    const size_t obase = (size_t)(q0 + wid * 16 + rsub) * D_MODEL + (size_t)h * HEAD_DIM;
#pragma unroll
    for (int j = 0; j < 16; j++) {
        const int col = j * 8 + csub;
#pragma unroll
        for (int half = 0; half < 2; half++) {
            const size_t off = obase + (size_t)(half * 8) * D_MODEL + col;
            float v0 = accO[j][2 * half + 0] * (half ? inv1 : inv0);
            float v1 = accO[j][2 * half + 1] * (half ? inv1 : inv0);
            float h0 = __bfloat162float(__float2bfloat16(v0));
            float h1 = __bfloat162float(__float2bfloat16(v1));
            *reinterpret_cast<uint32_t*>(g_Ohi + off) = pack_bf16x2(h0, h1);
            *reinterpret_cast<uint32_t*>(g_Olo + off) = pack_bf16x2(v0 - h0, v1 - h1);
        }
    }
}

// ---------------------------------------------------------------------------
// Launch
// ---------------------------------------------------------------------------
extern "C" void kernel_launch(void* const* d_in, const int* in_sizes, int n_in,
                              void* d_out, int out_size)
{
    const float* X  = (const float*)d_in[0];
    const float* Wq = (const float*)d_in[1];
    const float* Wk = (const float*)d_in[2];
    const float* Wv = (const float*)d_in[3];
    const float* Wo = (const float*)d_in[4];
    float* out = (float*)d_out;

    cudaFuncSetAttribute(qkv_gemm_fused, cudaFuncAttributeMaxDynamicSharedMemorySize, GEMM_SMEM);
    cudaFuncSetAttribute(out_gemm, cudaFuncAttributeMaxDynamicSharedMemorySize, GEMM_SMEM);
    cudaFuncSetAttribute(mha_fa_mma, cudaFuncAttributeMaxDynamicSharedMemorySize, ATT_SMEM);

    const int nElem = S_LEN * D_MODEL;

    // 1) split X; transpose+split weights
    split_x_kernel<<<nElem / 256, 256>>>(X);
    dim3 wb(32, 8), wg(D_MODEL / 32, D_MODEL / 32, 4);
    wsplit_t_kernel<<<wg, wb>>>(Wq, Wk, Wv, Wo);

    // 2) fused QKV projections (Q/K write bf16 splits directly; V fp32)
    dim3 gq(D_MODEL / 128, S_LEN / 128, 3);
    qkv_gemm_fused<<<gq, 256, GEMM_SMEM>>>();

    // 3) V transpose+split for attention
    dim3 vb(32, 8), vg(D_MODEL / 32, S_LEN / 32);
    vt_split_kernel<<<vg, vb>>>();

    // 4) causal flash attention on tensor cores (double-buffered K/V, ldmatrix)
    dim3 gatt(S_LEN / AQ, N_HEADS);
    mha_fa_mma<<<gatt, 256, ATT_SMEM>>>();

    // 5) output projection straight to harness buffer
    dim3 go(D_MODEL / 128, S_LEN / 128);
    out_gemm<<<go, 256, GEMM_SMEM>>>(out);
}

// round 16
// speedup vs baseline: 1.0175x; 1.0175x over previous
#include <cuda_runtime.h>
#include <cuda_bf16.h>
#include <math.h>
#include <stdint.h>

// Problem constants (fixed by the reference: B=1, S=4096, D=2048, H=16)
#define S_LEN    4096
#define D_MODEL  2048
#define KDIM     2048
#define N_HEADS  16
#define HEAD_DIM 128

// ---------------------------------------------------------------------------
// Scratch (__device__ globals; allocation-free rule)
// ---------------------------------------------------------------------------
__device__ float g_V[(size_t)S_LEN * D_MODEL];

__device__ __nv_bfloat16 g_Xhi[(size_t)S_LEN * D_MODEL];
__device__ __nv_bfloat16 g_Xlo[(size_t)S_LEN * D_MODEL];
__device__ __nv_bfloat16 g_Ohi[(size_t)S_LEN * D_MODEL];
__device__ __nv_bfloat16 g_Olo[(size_t)S_LEN * D_MODEL];
__device__ __nv_bfloat16 g_Wthi[(size_t)4 * D_MODEL * D_MODEL];
__device__ __nv_bfloat16 g_Wtlo[(size_t)4 * D_MODEL * D_MODEL];

// attention operands (bf16 hi/lo). Q pre-scaled by 1/sqrt(hd).
__device__ __nv_bfloat16 g_Qhi[(size_t)S_LEN * D_MODEL];
__device__ __nv_bfloat16 g_Qlo[(size_t)S_LEN * D_MODEL];
__device__ __nv_bfloat16 g_Khi[(size_t)S_LEN * D_MODEL];
__device__ __nv_bfloat16 g_Klo[(size_t)S_LEN * D_MODEL];
// V transposed per head: Vt[c][s] where c = h*128 + d  -> [D_MODEL][S_LEN]
__device__ __nv_bfloat16 g_Vthi[(size_t)D_MODEL * S_LEN];
__device__ __nv_bfloat16 g_Vtlo[(size_t)D_MODEL * S_LEN];

// ---------------------------------------------------------------------------
// Portable helpers (sm_80+): cp.async + mma.sync bf16 + ldmatrix
// ---------------------------------------------------------------------------
__device__ __forceinline__ uint32_t smem_to_u32(const void* p) {
    uint32_t a;
    asm("{ .reg .u64 t; cvta.to.shared.u64 t, %1; cvt.u32.u64 %0, t; }" : "=r"(a) : "l"(p));
    return a;
}
__device__ __forceinline__ void cp_async16(uint32_t dst, const void* src) {
    asm volatile("cp.async.cg.shared.global [%0], [%1], 16;" :: "r"(dst), "l"(src));
}
#define CP_COMMIT() asm volatile("cp.async.commit_group;" ::: "memory")
#define CP_WAIT1()  asm volatile("cp.async.wait_group 1;" ::: "memory")
#define CP_WAIT0()  asm volatile("cp.async.wait_group 0;" ::: "memory")

__device__ __forceinline__ void mma_bf16(float* c, const uint32_t* a, const uint32_t* b) {
    asm volatile(
        "mma.sync.aligned.m16n8k16.row.col.f32.bf16.bf16.f32 "
        "{%0,%1,%2,%3}, {%4,%5,%6,%7}, {%8,%9}, {%0,%1,%2,%3};"
        : "+f"(c[0]), "+f"(c[1]), "+f"(c[2]), "+f"(c[3])
        : "r"(a[0]), "r"(a[1]), "r"(a[2]), "r"(a[3]), "r"(b[0]), "r"(b[1]));
}
__device__ __forceinline__ void ldsm_x4(uint32_t& r0, uint32_t& r1, uint32_t& r2, uint32_t& r3,
                                        uint32_t addr) {
    asm volatile("ldmatrix.sync.aligned.m8n8.x4.shared.b16 {%0,%1,%2,%3}, [%4];"
                 : "=r"(r0), "=r"(r1), "=r"(r2), "=r"(r3) : "r"(addr));
}
__device__ __forceinline__ uint32_t pack_bf16x2(float lo, float hi) {
    __nv_bfloat162 v = __float22bfloat162_rn(make_float2(lo, hi));
    return *reinterpret_cast<uint32_t*>(&v);
}

// ---------------------------------------------------------------------------
// Prep kernels
// ---------------------------------------------------------------------------
__global__ void split_x_kernel(const float* __restrict__ X) {
    size_t i = (size_t)blockIdx.x * blockDim.x + threadIdx.x;
    float v = X[i];
    __nv_bfloat16 h = __float2bfloat16(v);
    g_Xhi[i] = h;
    g_Xlo[i] = __float2bfloat16(v - __bfloat162float(h));
}
__global__ void wsplit_t_kernel(const float* __restrict__ Wq, const float* __restrict__ Wk,
                                const float* __restrict__ Wv, const float* __restrict__ Wo) {
    __shared__ float tile[32][33];
    const int w = blockIdx.z;
    const float* W = (w == 0) ? Wq : (w == 1) ? Wk : (w == 2) ? Wv : Wo;
    const size_t off = (size_t)w * D_MODEL * D_MODEL;
    const int n0 = blockIdx.x * 32, k0 = blockIdx.y * 32;
    const int tx = threadIdx.x, ty = threadIdx.y;  // (32, 8)
#pragma unroll
    for (int i = 0; i < 32; i += 8)
        tile[ty + i][tx] = W[(size_t)(k0 + ty + i) * D_MODEL + n0 + tx];
    __syncthreads();
#pragma unroll
    for (int i = 0; i < 32; i += 8) {
        int n = n0 + ty + i, k = k0 + tx;
        float v = tile[tx][ty + i];
        __nv_bfloat16 h = __float2bfloat16(v);
        g_Wthi[off + (size_t)n * KDIM + k] = h;
        g_Wtlo[off + (size_t)n * KDIM + k] = __float2bfloat16(v - __bfloat162float(h));
    }
}
// V [S][D] fp32 -> Vt hi/lo [D][S] bf16 (coalesced 32x32 transpose)
__global__ void vt_split_kernel() {
    __shared__ float tile[32][33];
    const int s0 = blockIdx.y * 32, c0 = blockIdx.x * 32;
    const int tx = threadIdx.x, ty = threadIdx.y;  // (32, 8)
#pragma unroll
    for (int i = 0; i < 32; i += 8)
        tile[ty + i][tx] = g_V[(size_t)(s0 + ty + i) * D_MODEL + c0 + tx];
    __syncthreads();
#pragma unroll
    for (int i = 0; i < 32; i += 8) {
        int c = c0 + ty + i, s = s0 + tx;
        float v = tile[tx][ty + i];
        __nv_bfloat16 h = __float2bfloat16(v);
        g_Vthi[(size_t)c * S_LEN + s] = h;
        g_Vtlo[(size_t)c * S_LEN + s] = __float2bfloat16(v - __bfloat162float(h));
    }
}

// ---------------------------------------------------------------------------
// bf16x3 tensor-core GEMM core (compute accumulators for one 128x128 tile).
// Block 128x128xK32, 256 threads (8 warps 2x4), warp tile 64x32.
// Fragment loads via ldmatrix.x4 (12 LDSM/ks vs 48 LDS.32/ks).
// (R14 configuration — K32, 2 CTA/SM, single-buffered fragments.)
// ---------------------------------------------------------------------------
#define LDSW 40
#define TILE_B (128 * LDSW * 2)
#define STAGE_B (4 * TILE_B)
#define GEMM_SMEM (2 * STAGE_B)
#define NSTAGE (KDIM / 32)

__device__ __forceinline__ void gemm_core(const __nv_bfloat16* __restrict__ Ah,
                                          const __nv_bfloat16* __restrict__ Al,
                                          const __nv_bfloat16* __restrict__ Bh,
                                          const __nv_bfloat16* __restrict__ Bl,
                                          char* sm_, float acc[4][4][4])
{
    const int t = threadIdx.x;
    const int lane = t & 31, wid = t >> 5;
    const int wm = wid >> 2, wn = wid & 3;
    const uint32_t sbase = smem_to_u32(sm_);

#pragma unroll
    for (int mi = 0; mi < 4; mi++)
#pragma unroll
        for (int ni = 0; ni < 4; ni++)
#pragma unroll
            for (int e = 0; e < 4; e++) acc[mi][ni][e] = 0.0f;

    const int ldr = t >> 2;
    const int kc  = t & 3;
    const __nv_bfloat16* srcs[4] = { Ah, Al, Bh, Bl };

    // ldmatrix lane-address components (per warp):
    const int lr = lane & 7;       // row within 8x8 matrix
    const int lg = lane >> 3;      // matrix group 0..3
    const int a_row_off = (lg & 1) * 8 + lr;
    const int a_col_off = (lg >> 1) * 8;
    const int b_row_off = ((lg >> 1) & 1) * 8 + lr;
    const int b_col_off = (lg & 1) * 8;

    {
        const uint32_t dbase = sbase;
#pragma unroll
        for (int j = 0; j < 8; j++) {
            const int tile = j >> 1;
            const int row = (j & 1) * 64 + ldr;
            cp_async16(dbase + tile * TILE_B + row * 80 + kc * 16,
                       srcs[tile] + (size_t)row * KDIM + kc * 8);
        }
        CP_COMMIT();
    }

    for (int kt = 0; kt < NSTAGE; kt++) {
        if (kt + 1 < NSTAGE) {
            const int k0 = (kt + 1) * 32;
            const uint32_t dbase = sbase + ((kt + 1) & 1) * STAGE_B;
#pragma unroll
            for (int j = 0; j < 8; j++) {
                const int tile = j >> 1;
                const int row = (j & 1) * 64 + ldr;
                cp_async16(dbase + tile * TILE_B + row * 80 + kc * 16,
                           srcs[tile] + (size_t)row * KDIM + k0 + kc * 8);
            }
            CP_COMMIT();
            CP_WAIT1();
        } else {
            CP_WAIT0();
        }
        __syncthreads();

        const uint32_t stb = sbase + (kt & 1) * STAGE_B;
        const uint32_t sAh = stb;
        const uint32_t sAl = stb + TILE_B;
        const uint32_t sBh = stb + 2 * TILE_B;
        const uint32_t sBl = stb + 3 * TILE_B;

#pragma unroll
        for (int ks = 0; ks < 2; ks++) {
            const int kbase = ks * 16;

            uint32_t ah[4][4], al[4][4], bh[4][2], bl[4][2];
#pragma unroll
            for (int mi = 0; mi < 4; mi++) {
                const int r = wm * 64 + mi * 16 + a_row_off;
                const uint32_t off = (uint32_t)(r * LDSW + kbase + a_col_off) * 2;
                ldsm_x4(ah[mi][0], ah[mi][1], ah[mi][2], ah[mi][3], sAh + off);
                ldsm_x4(al[mi][0], al[mi][1], al[mi][2], al[mi][3], sAl + off);
            }
#pragma unroll
            for (int pair = 0; pair < 2; pair++) {
                const int n = wn * 32 + pair * 16 + b_row_off;
                const uint32_t off = (uint32_t)(n * LDSW + kbase + b_col_off) * 2;
                ldsm_x4(bh[2 * pair][0], bh[2 * pair][1],
                        bh[2 * pair + 1][0], bh[2 * pair + 1][1], sBh + off);
                ldsm_x4(bl[2 * pair][0], bl[2 * pair][1],
                        bl[2 * pair + 1][0], bl[2 * pair + 1][1], sBl + off);
            }
#pragma unroll
            for (int mi = 0; mi < 4; mi++)
#pragma unroll
                for (int ni = 0; ni < 4; ni++) {
                    mma_bf16(acc[mi][ni], ah[mi], bh[ni]);
                    mma_bf16(acc[mi][ni], ah[mi], bl[ni]);
                    mma_bf16(acc[mi][ni], al[mi], bh[ni]);
                }
        }
        __syncthreads();
    }
}

// Fused QKV: z=0 -> Q (scaled, bf16 split out), z=1 -> K (split out), z=2 -> V (fp32)
__global__ __launch_bounds__(256, 2)
void qkv_gemm_fused()
{
    extern __shared__ char sm_[];
    const int z = blockIdx.z;
    const int bm = blockIdx.y, bn = blockIdx.x;
    const size_t woff = (size_t)z * D_MODEL * D_MODEL;

    float acc[4][4][4];
    gemm_core(g_Xhi + (size_t)(bm * 128) * KDIM,
              g_Xlo + (size_t)(bm * 128) * KDIM,
              g_Wthi + woff + (size_t)(bn * 128) * KDIM,
              g_Wtlo + woff + (size_t)(bn * 128) * KDIM,
              sm_, acc);

    const int t = threadIdx.x;
    const int lane = t & 31, wid = t >> 5;
    const int wm = wid >> 2, wn = wid & 3;
    const int rsub = lane >> 2, csub = (lane & 3) * 2;
    const int rowB = bm * 128 + wm * 64;
    const int colB = bn * 128 + wn * 32;

    if (z == 2) {
        float* Cb = g_V + (size_t)rowB * D_MODEL + colB;
#pragma unroll
        for (int mi = 0; mi < 4; mi++)
#pragma unroll
            for (int ni = 0; ni < 4; ni++) {
                const int row = mi * 16 + rsub;
                const int col = ni * 8 + csub;
                *reinterpret_cast<float2*>(Cb + (size_t)row * D_MODEL + col) =
                    make_float2(acc[mi][ni][0], acc[mi][ni][1]);
                *reinterpret_cast<float2*>(Cb + (size_t)(row + 8) * D_MODEL + col) =
                    make_float2(acc[mi][ni][2], acc[mi][ni][3]);
            }
    } else {
        const float scale = (z == 0) ? 0.08838834764831845f : 1.0f;
        __nv_bfloat16* Hi = (z == 0) ? g_Qhi : g_Khi;
        __nv_bfloat16* Lo = (z == 0) ? g_Qlo : g_Klo;
#pragma unroll
        for (int mi = 0; mi < 4; mi++)
#pragma unroll
            for (int ni = 0; ni < 4; ni++) {
                const int row = rowB + mi * 16 + rsub;
                const int col = colB + ni * 8 + csub;
#pragma unroll
                for (int half = 0; half < 2; half++) {
                    const int r = row + half * 8;
                    float v0 = acc[mi][ni][2 * half + 0] * scale;
                    float v1 = acc[mi][ni][2 * half + 1] * scale;
                    float h0 = __bfloat162float(__float2bfloat16(v0));
                    float h1 = __bfloat162float(__float2bfloat16(v1));
                    *reinterpret_cast<uint32_t*>(Hi + (size_t)r * D_MODEL + col) =
                        pack_bf16x2(h0, h1);
                    *reinterpret_cast<uint32_t*>(Lo + (size_t)r * D_MODEL + col) =
                        pack_bf16x2(v0 - h0, v1 - h1);
                }
            }
    }
}

// Output projection: fp32 epilogue straight to harness output
__global__ __launch_bounds__(256, 2)
void out_gemm(float* __restrict__ out)
{
    extern __shared__ char sm_[];
    const int bm = blockIdx.y, bn = blockIdx.x;
    const size_t woff = (size_t)3 * D_MODEL * D_MODEL;

    float acc[4][4][4];
    gemm_core(g_Ohi + (size_t)(bm * 128) * KDIM,
              g_Olo + (size_t)(bm * 128) * KDIM,
              g_Wthi + woff + (size_t)(bn * 128) * KDIM,
              g_Wtlo + woff + (size_t)(bn * 128) * KDIM,
              sm_, acc);

    const int t = threadIdx.x;
    const int lane = t & 31, wid = t >> 5;
    const int wm = wid >> 2, wn = wid & 3;
    const int rsub = lane >> 2, csub = (lane & 3) * 2;

    float* Cb = out + (size_t)(bm * 128 + wm * 64) * D_MODEL + bn * 128 + wn * 32;
#pragma unroll
    for (int mi = 0; mi < 4; mi++)
#pragma unroll
        for (int ni = 0; ni < 4; ni++) {
            const int row = mi * 16 + rsub;
            const int col = ni * 8 + csub;
            *reinterpret_cast<float2*>(Cb + (size_t)row * D_MODEL + col) =
                make_float2(acc[mi][ni][0], acc[mi][ni][1]);
            *reinterpret_cast<float2*>(Cb + (size_t)(row + 8) * D_MODEL + col) =
                make_float2(acc[mi][ni][2], acc[mi][ni][3]);
        }
}

// ---------------------------------------------------------------------------
// FA2-style attention on mma.sync (bf16 split precision).
// CTA = 128 queries x 1 head, 256 threads, 8 warps x 16 query rows.
// KV tiles of 64 keys, DOUBLE-BUFFERED via cp.async. Fragment loads via
// ldmatrix.x4. Online softmax in fp32; P kept in registers.
// Epilogue writes O directly as bf16 hi/lo splits.
// ---------------------------------------------------------------------------
#define AQ 128
#define AK 64
#define QSTR 136   // bf16 elems per Q/K smem row (272 B) -> conflict-free
#define VSTR 72    // bf16 elems per Vt smem row (144 B) -> conflict-free

#define SM_QHI 0
#define SM_QLO (SM_QHI + AQ * QSTR * 2)          // 34816
#define SM_KV  (SM_QLO + AQ * QSTR * 2)          // 69632: start of KV stages
#define KV_KHI 0
#define KV_KLO (KV_KHI + AK * QSTR * 2)          // 17408
#define KV_VHI (KV_KLO + AK * QSTR * 2)          // 34816
#define KV_VLO (KV_VHI + HEAD_DIM * VSTR * 2)    // 53248
#define KV_STAGE (KV_VLO + HEAD_DIM * VSTR * 2)  // 71680
#define ATT_SMEM (SM_KV + 2 * KV_STAGE)          // 212992

__global__ __launch_bounds__(256, 1)
void mha_fa_mma()
{
    extern __shared__ char sm_[];
    const uint32_t sbase = smem_to_u32(sm_);
    const int t = threadIdx.x;
    const int lane = t & 31, wid = t >> 5;
    const int ib = gridDim.x - 1 - blockIdx.x;   // reversed: long CTAs first
    const int h = blockIdx.y;
    const int q0 = ib * AQ;
    const int rsub = lane >> 2, csub = (lane & 3) * 2;

    // ldmatrix lane-address components
    const int lr = lane & 7;
    const int lg = lane >> 3;
    const int a_row_off = (lg & 1) * 8 + lr;     // A operand (Q)
    const int a_col_off = (lg >> 1) * 8;
    const int b_row_off = ((lg >> 1) & 1) * 8 + lr;  // B operand (K / Vt)
    const int b_col_off = (lg & 1) * 8;

    const uint32_t sQh = sbase + SM_QHI;
    const uint32_t sQl = sbase + SM_QLO;

    // ---- load Q tile (once), group 0 ----
    {
        const size_t gq = (size_t)q0 * D_MODEL + (size_t)h * HEAD_DIM;
#pragma unroll
        for (int i = 0; i < 8; i++) {
            const int idx = t + i * 256;
            const int row = idx >> 4, c = idx & 15;
            cp_async16(sQh + row * (QSTR * 2) + c * 16,
                       g_Qhi + gq + (size_t)row * D_MODEL + c * 8);
            cp_async16(sQl + row * (QSTR * 2) + c * 16,
                       g_Qlo + gq + (size_t)row * D_MODEL + c * 8);
        }
        CP_COMMIT();
    }

    const int nTiles = 2 * ib + 2;

    // ---- helper lambda: issue K/V loads for tile jb into given stage ----
    auto load_kv = [&](int jb, int stage) {
        const uint32_t kvb = sbase + SM_KV + stage * KV_STAGE;
        const int k0 = jb * AK;
        const size_t gk = (size_t)k0 * D_MODEL + (size_t)h * HEAD_DIM;
#pragma unroll
        for (int i = 0; i < 4; i++) {
            const int idx = t + i * 256;
            const int row = idx >> 4, c = idx & 15;
            cp_async16(kvb + KV_KHI + row * (QSTR * 2) + c * 16,
                       g_Khi + gk + (size_t)row * D_MODEL + c * 8);
            cp_async16(kvb + KV_KLO + row * (QSTR * 2) + c * 16,
                       g_Klo + gk + (size_t)row * D_MODEL + c * 8);
        }
        const size_t gv = (size_t)h * HEAD_DIM * S_LEN + k0;
#pragma unroll
        for (int i = 0; i < 4; i++) {
            const int idx = t + i * 256;
            const int row = idx >> 3, c = idx & 7;
            cp_async16(kvb + KV_VHI + row * (VSTR * 2) + c * 16,
                       g_Vthi + gv + (size_t)row * S_LEN + c * 8);
            cp_async16(kvb + KV_VLO + row * (VSTR * 2) + c * 16,
                       g_Vtlo + gv + (size_t)row * S_LEN + c * 8);
        }
        CP_COMMIT();
    };

    // preload tile 0 into stage 0 (group 1)
    load_kv(0, 0);

    float accO[16][4];
#pragma unroll
    for (int j = 0; j < 16; j++)
#pragma unroll
        for (int e = 0; e < 4; e++) accO[j][e] = 0.0f;
    float m0 = -1e30f, m1 = -1e30f, l0 = 0.0f, l1 = 0.0f;

    for (int jb = 0; jb < nTiles; jb++) {
        const int buf = jb & 1;
        if (jb + 1 < nTiles) {
            load_kv(jb + 1, buf ^ 1);
            CP_WAIT1();
        } else {
            CP_WAIT0();
        }
        __syncthreads();

        const uint32_t kvb = sbase + SM_KV + buf * KV_STAGE;
        const uint32_t sKh = kvb + KV_KHI;
        const uint32_t sKl = kvb + KV_KLO;
        const uint32_t sVh = kvb + KV_VHI;
        const uint32_t sVl = kvb + KV_VLO;
        const int k0 = jb * AK;

        // ---- S = Q K^T (bf16x3, ldmatrix fragments) ----
        float accS[8][4];
#pragma unroll
        for (int j = 0; j < 8; j++)
#pragma unroll
            for (int e = 0; e < 4; e++) accS[j][e] = 0.0f;

#pragma unroll
        for (int ks = 0; ks < 8; ks++) {
            const int kbase = ks * 16;
            uint32_t ah[4], al[4];
            {
                const int r = wid * 16 + a_row_off;
                const uint32_t off = (uint32_t)(r * QSTR + kbase + a_col_off) * 2;
                ldsm_x4(ah[0], ah[1], ah[2], ah[3], sQh + off);
                ldsm_x4(al[0], al[1], al[2], al[3], sQl + off);
            }
#pragma unroll
            for (int pair = 0; pair < 4; pair++) {
                const int n = pair * 16 + b_row_off;
                const uint32_t off = (uint32_t)(n * QSTR + kbase + b_col_off) * 2;
                uint32_t bh0[2], bh1[2], bl0[2], bl1[2];
                ldsm_x4(bh0[0], bh0[1], bh1[0], bh1[1], sKh + off);
                ldsm_x4(bl0[0], bl0[1], bl1[0], bl1[1], sKl + off);
                mma_bf16(accS[2 * pair], ah, bh0);
                mma_bf16(accS[2 * pair], ah, bl0);
                mma_bf16(accS[2 * pair], al, bh0);
                mma_bf16(accS[2 * pair + 1], ah, bh1);
                mma_bf16(accS[2 * pair + 1], ah, bl1);
                mma_bf16(accS[2 * pair + 1], al, bh1);
            }
        }

        // ---- causal mask (only the two diagonal tiles) ----
        if (jb >= 2 * ib) {
            const int row0 = q0 + wid * 16 + rsub;
            const int row1 = row0 + 8;
#pragma unroll
            for (int j = 0; j < 8; j++) {
                const int c0 = k0 + j * 8 + csub;
                if (c0 > row0)     accS[j][0] = -1e30f;
                if (c0 + 1 > row0) accS[j][1] = -1e30f;
                if (c0 > row1)     accS[j][2] = -1e30f;
                if (c0 + 1 > row1) accS[j][3] = -1e30f;
            }
        }

        // ---- online softmax ----
        float mx0 = -1e30f, mx1 = -1e30f;
#pragma unroll
        for (int j = 0; j < 8; j++) {
            mx0 = fmaxf(mx0, fmaxf(accS[j][0], accS[j][1]));
            mx1 = fmaxf(mx1, fmaxf(accS[j][2], accS[j][3]));
        }
        mx0 = fmaxf(mx0, __shfl_xor_sync(0xffffffffu, mx0, 1));
        mx0 = fmaxf(mx0, __shfl_xor_sync(0xffffffffu, mx0, 2));
        mx1 = fmaxf(mx1, __shfl_xor_sync(0xffffffffu, mx1, 1));
        mx1 = fmaxf(mx1, __shfl_xor_sync(0xffffffffu, mx1, 2));

        const float mn0 = fmaxf(m0, mx0);
        const float mn1 = fmaxf(m1, mx1);
        const float al0 = __expf(m0 - mn0);
        const float al1 = __expf(m1 - mn1);
        m0 = mn0; m1 = mn1;

        float s0 = 0.0f, s1 = 0.0f;
#pragma unroll
        for (int j = 0; j < 8; j++) {
            accS[j][0] = __expf(accS[j][0] - m0);
            accS[j][1] = __expf(accS[j][1] - m0);
            accS[j][2] = __expf(accS[j][2] - m1);
            accS[j][3] = __expf(accS[j][3] - m1);
            s0 += accS[j][0] + accS[j][1];
            s1 += accS[j][2] + accS[j][3];
        }
        s0 += __shfl_xor_sync(0xffffffffu, s0, 1);
        s0 += __shfl_xor_sync(0xffffffffu, s0, 2);
        s1 += __shfl_xor_sync(0xffffffffu, s1, 1);
        s1 += __shfl_xor_sync(0xffffffffu, s1, 2);
        l0 = l0 * al0 + s0;
        l1 = l1 * al1 + s1;

#pragma unroll
        for (int j = 0; j < 16; j++) {
            accO[j][0] *= al0; accO[j][1] *= al0;
            accO[j][2] *= al1; accO[j][3] *= al1;
        }

        // ---- O += P V (bf16x3; P fragments straight from accS) ----
#pragma unroll
        for (int ks = 0; ks < 4; ks++) {
            uint32_t ph[4], pl[4];
            {
                const float* f0 = accS[2 * ks];
                const float* f1 = accS[2 * ks + 1];
                float h00 = __bfloat162float(__float2bfloat16(f0[0]));
                float h01 = __bfloat162float(__float2bfloat16(f0[1]));
                float h02 = __bfloat162float(__float2bfloat16(f0[2]));
                float h03 = __bfloat162float(__float2bfloat16(f0[3]));
                float h10 = __bfloat162float(__float2bfloat16(f1[0]));
                float h11 = __bfloat162float(__float2bfloat16(f1[1]));
                float h12 = __bfloat162float(__float2bfloat16(f1[2]));
                float h13 = __bfloat162float(__float2bfloat16(f1[3]));
                ph[0] = pack_bf16x2(h00, h01);
                ph[1] = pack_bf16x2(h02, h03);
                ph[2] = pack_bf16x2(h10, h11);
                ph[3] = pack_bf16x2(h12, h13);
                pl[0] = pack_bf16x2(f0[0] - h00, f0[1] - h01);
                pl[1] = pack_bf16x2(f0[2] - h02, f0[3] - h03);
                pl[2] = pack_bf16x2(f1[0] - h10, f1[1] - h11);
                pl[3] = pack_bf16x2(f1[2] - h12, f1[3] - h13);
            }
            const int kbase = ks * 16;
#pragma unroll
            for (int pair = 0; pair < 8; pair++) {
                const int n = pair * 16 + b_row_off;
                const uint32_t off = (uint32_t)(n * VSTR + kbase + b_col_off) * 2;
                uint32_t vh0[2], vh1[2], vl0[2], vl1[2];
                ldsm_x4(vh0[0], vh0[1], vh1[0], vh1[1], sVh + off);
                ldsm_x4(vl0[0], vl0[1], vl1[0], vl1[1], sVl + off);
                mma_bf16(accO[2 * pair], ph, vh0);
                mma_bf16(accO[2 * pair], ph, vl0);
                mma_bf16(accO[2 * pair], pl, vh0);
                mma_bf16(accO[2 * pair + 1], ph, vh1);
                mma_bf16(accO[2 * pair + 1], ph, vl1);
                mma_bf16(accO[2 * pair + 1], pl, vh1);
            }
        }
        __syncthreads();   // all warps done reading this stage before it is re-filled
    }

    // ---- normalize + write O directly as bf16 hi/lo splits ----
    const float inv0 = 1.0f / l0;
    const float inv1 = 1.0f / l1;
    const size_t obase = (size_t)(q0 + wid * 16 + rsub) * D_MODEL + (size_t)h * HEAD_DIM;
#pragma unroll
    for (int j = 0; j < 16; j++) {
        const int col = j * 8 + csub;
#pragma unroll
        for (int half = 0; half < 2; half++) {
            const size_t off = obase + (size_t)(half * 8) * D_MODEL + col;
            float v0 = accO[j][2 * half + 0] * (half ? inv1 : inv0);
            float v1 = accO[j][2 * half + 1] * (half ? inv1 : inv0);
            float h0 = __bfloat162float(__float2bfloat16(v0));
            float h1 = __bfloat162float(__float2bfloat16(v1));
            *reinterpret_cast<uint32_t*>(g_Ohi + off) = pack_bf16x2(h0, h1);
            *reinterpret_cast<uint32_t*>(g_Olo + off) = pack_bf16x2(v0 - h0, v1 - h1);
        }
    }
}

// ---------------------------------------------------------------------------
// Launch
// ---------------------------------------------------------------------------
extern "C" void kernel_launch(void* const* d_in, const int* in_sizes, int n_in,
                              void* d_out, int out_size)
{
    const float* X  = (const float*)d_in[0];
    const float* Wq = (const float*)d_in[1];
    const float* Wk = (const float*)d_in[2];
    const float* Wv = (const float*)d_in[3];
    const float* Wo = (const float*)d_in[4];
    float* out = (float*)d_out;

    cudaFuncSetAttribute(qkv_gemm_fused, cudaFuncAttributeMaxDynamicSharedMemorySize, GEMM_SMEM);
    cudaFuncSetAttribute(out_gemm, cudaFuncAttributeMaxDynamicSharedMemorySize, GEMM_SMEM);
    cudaFuncSetAttribute(mha_fa_mma, cudaFuncAttributeMaxDynamicSharedMemorySize, ATT_SMEM);

    const int nElem = S_LEN * D_MODEL;

    // 1) split X; transpose+split weights
    split_x_kernel<<<nElem / 256, 256>>>(X);
    dim3 wb(32, 8), wg(D_MODEL / 32, D_MODEL / 32, 4);
    wsplit_t_kernel<<<wg, wb>>>(Wq, Wk, Wv, Wo);

    // 2) fused QKV projections (Q/K write bf16 splits directly; V fp32)
    dim3 gq(D_MODEL / 128, S_LEN / 128, 3);
    qkv_gemm_fused<<<gq, 256, GEMM_SMEM>>>();

    // 3) V transpose+split for attention
    dim3 vb(32, 8), vg(D_MODEL / 32, S_LEN / 32);
    vt_split_kernel<<<vg, vb>>>();

    // 4) causal flash attention on tensor cores (double-buffered K/V, ldmatrix)
    dim3 gatt(S_LEN / AQ, N_HEADS);
    mha_fa_mma<<<gatt, 256, ATT_SMEM>>>();

    // 5) output projection straight to harness buffer
    dim3 go(D_MODEL / 128, S_LEN / 128);
    out_gemm<<<go, 256, GEMM_SMEM>>>(out);
}